// round 1
// baseline (speedup 1.0000x reference)
#include <cuda_runtime.h>
#include <math.h>
#include <stdint.h>

// Problem dims (fixed)
#define Bz   256
#define Pz   196
#define Hz   1024
#define Az   512
#define MBIG (Bz * Pz)   // 50176, divisible by 128 (392 tiles)

// ---------------- device scratch (no allocations allowed) ----------------
__device__ float g_sent_aff[Bz * Hz];   // relu(st @ W_sen_aff + b)
__device__ float g_hid_aff [Bz * Hz];   // tanh(dec @ W_h_aff + b)
__device__ float g_sent_att[Bz * Az];   // sent_aff @ W_sen_att + b
__device__ float g_hid_att [Bz * Az];   // hid_aff  @ W_h_att  + b
__device__ float g_alpha_part[4 * MBIG];// per-N-chunk partial alpha (deterministic)
__device__ float g_ctx     [Bz * Hz];   // context + hidden_affine

// ---------------- generic small GEMM: C = act(A@B + bias) ----------------
// BM=BN=64, BK=16, 256 threads (16x16), thread tile 4x4.
// ACT: 0=none, 1=relu, 2=tanh
template <int ACT>
__global__ void gemm64(const float* __restrict__ A, const float* __restrict__ Bw,
                       const float* __restrict__ bias, float* __restrict__ C,
                       int M, int N, int K)
{
    __shared__ __align__(16) float As[16][68];
    __shared__ __align__(16) float Bs[16][68];
    const int tid = threadIdx.x;
    const int tx = tid & 15, ty = tid >> 4;
    const int m0 = blockIdx.y * 64, n0 = blockIdx.x * 64;

    const int arow = tid >> 2, acg = (tid & 3) * 4;  // A tile: 64 rows x 16 cols
    const int brow = tid >> 4, bcol = (tid & 15) * 4; // B tile: 16 rows x 64 cols

    float acc[4][4] = {};

    for (int k0 = 0; k0 < K; k0 += 16) {
        float4 av = *(const float4*)&A[(size_t)(m0 + arow) * K + k0 + acg];
        As[acg + 0][arow] = av.x; As[acg + 1][arow] = av.y;
        As[acg + 2][arow] = av.z; As[acg + 3][arow] = av.w;
        *(float4*)&Bs[brow][bcol] =
            *(const float4*)&Bw[(size_t)(k0 + brow) * N + n0 + bcol];
        __syncthreads();
#pragma unroll
        for (int k = 0; k < 16; k++) {
            float4 a4 = *(const float4*)&As[k][ty * 4];
            float4 b4 = *(const float4*)&Bs[k][tx * 4];
            float a[4] = {a4.x, a4.y, a4.z, a4.w};
            float b[4] = {b4.x, b4.y, b4.z, b4.w};
#pragma unroll
            for (int i = 0; i < 4; i++)
#pragma unroll
                for (int j = 0; j < 4; j++) acc[i][j] += a[i] * b[j];
        }
        __syncthreads();
    }

#pragma unroll
    for (int i = 0; i < 4; i++) {
        int m = m0 + ty * 4 + i;
#pragma unroll
        for (int j = 0; j < 4; j++) {
            int n = n0 + tx * 4 + j;
            float v = acc[i][j] + bias[n];
            if (ACT == 1) v = fmaxf(v, 0.f);
            if (ACT == 2) v = tanhf(v);
            C[(size_t)m * N + n] = v;
        }
    }
}

// ---------------- fused big kernel ----------------
// For each flattened row m = b*196+p, N-chunk c (128 cols of A-dim):
//   g_alpha_part[c*MBIG+m] = sum_{n in chunk} tanh(Sp[m,:]@Wv[:,n] + bv[n]
//                                                 + hid_att[b,n]) * Wa[n]
// BM=128, BN=128, BK=16, 256 threads (16x16), thread tile 8x8.
__global__ void big_attn_kernel(const float* __restrict__ Sp,  // (MBIG, 1024)
                                const float* __restrict__ Wv,  // (1024, 512)
                                const float* __restrict__ bv,  // (512)
                                const float* __restrict__ Wa)  // (512)
{
    __shared__ __align__(16) float As[16][132];
    __shared__ __align__(16) float Bs[16][132];
    const int tid = threadIdx.x;
    const int tx = tid & 15, ty = tid >> 4;
    const int m0 = blockIdx.x * 128;
    const int chunk = blockIdx.y;       // 0..3
    const int n0 = chunk * 128;

    float acc[8][8] = {};

    for (int k0 = 0; k0 < 1024; k0 += 16) {
#pragma unroll
        for (int s = 0; s < 2; s++) {
            int slot = tid + s * 256;               // 0..511
            int row = slot >> 2, cg = (slot & 3) * 4;
            float4 av = *(const float4*)&Sp[(size_t)(m0 + row) * 1024 + k0 + cg];
            As[cg + 0][row] = av.x; As[cg + 1][row] = av.y;
            As[cg + 2][row] = av.z; As[cg + 3][row] = av.w;
            int br = slot >> 5, bc = (slot & 31) * 4;
            *(float4*)&Bs[br][bc] =
                *(const float4*)&Wv[(size_t)(k0 + br) * 512 + n0 + bc];
        }
        __syncthreads();
#pragma unroll
        for (int k = 0; k < 16; k++) {
            float4 a0 = *(const float4*)&As[k][ty * 8];
            float4 a1 = *(const float4*)&As[k][ty * 8 + 4];
            float4 c0 = *(const float4*)&Bs[k][tx * 8];
            float4 c1 = *(const float4*)&Bs[k][tx * 8 + 4];
            float a[8] = {a0.x, a0.y, a0.z, a0.w, a1.x, a1.y, a1.z, a1.w};
            float b[8] = {c0.x, c0.y, c0.z, c0.w, c1.x, c1.y, c1.z, c1.w};
#pragma unroll
            for (int i = 0; i < 8; i++)
#pragma unroll
                for (int j = 0; j < 8; j++) acc[i][j] += a[i] * b[j];
        }
        __syncthreads();
    }

    // Epilogue: tanh(acc + bv + hid_att) dot Wa over this thread's 8 cols.
    float rowsum[8];
#pragma unroll
    for (int i = 0; i < 8; i++) {
        int m = m0 + ty * 8 + i;
        int bb = m / 196;
        float s = 0.f;
#pragma unroll
        for (int j = 0; j < 8; j++) {
            int n = n0 + tx * 8 + j;
            float v = tanhf(acc[i][j] + bv[n] + g_hid_att[bb * 512 + n]);
            s += v * Wa[n];
        }
        rowsum[i] = s;
    }

    // Reduce across the 16 tx lanes sharing each row (reuse As as scratch).
    float* red = &As[0][0];  // 2112 floats available, need 2048
    __syncthreads();
#pragma unroll
    for (int i = 0; i < 8; i++) red[(ty * 8 + i) * 16 + tx] = rowsum[i];
    __syncthreads();
    if (tid < 128) {
        float s = 0.f;
#pragma unroll
        for (int t = 0; t < 16; t++) s += red[tid * 16 + t];
        g_alpha_part[chunk * MBIG + m0 + tid] = s;
    }
}

// ---------------- softmax over 197 logits per batch ----------------
// Also computes the sentinel logit. Writes att_weights + beta into d_out.
__global__ void softmax_kernel(const float* __restrict__ Wa,
                               float* __restrict__ out_w,   // (B,197)
                               float* __restrict__ out_beta)// (B,1)
{
    const int b = blockIdx.x;
    const int tid = threadIdx.x;  // 256
    __shared__ float sh[256];
    __shared__ float vals[197];

    // sentinel logit: sum_a tanh(sent_att + hid_att) * Wa
    float s = 0.f;
    for (int a = tid; a < 512; a += 256)
        s += tanhf(g_sent_att[b * 512 + a] + g_hid_att[b * 512 + a]) * Wa[a];
    sh[tid] = s; __syncthreads();
    for (int off = 128; off > 0; off >>= 1) {
        if (tid < off) sh[tid] += sh[tid + off];
        __syncthreads();
    }
    float alpha_sent = sh[0];
    __syncthreads();

    float v = -INFINITY;
    if (tid < 196) {
        int m = b * 196 + tid;
        v = g_alpha_part[m] + g_alpha_part[MBIG + m] +
            g_alpha_part[2 * MBIG + m] + g_alpha_part[3 * MBIG + m];
        vals[tid] = v;
    } else if (tid == 196) {
        v = alpha_sent; vals[196] = v;
    }
    sh[tid] = v; __syncthreads();
    for (int off = 128; off > 0; off >>= 1) {
        if (tid < off) sh[tid] = fmaxf(sh[tid], sh[tid + off]);
        __syncthreads();
    }
    float mx = sh[0]; __syncthreads();

    float e = (tid < 197) ? expf(vals[tid] - mx) : 0.f;
    sh[tid] = e; __syncthreads();
    for (int off = 128; off > 0; off >>= 1) {
        if (tid < off) sh[tid] += sh[tid + off];
        __syncthreads();
    }
    float inv = 1.f / sh[0];
    if (tid < 197) {
        float w = e * inv;
        out_w[b * 197 + tid] = w;
        if (tid == 196) out_beta[b] = w;
    }
}

// ---------------- context: weighted sum over P + hidden_affine ----------------
__global__ void context_kernel(const float* __restrict__ Sp,
                               const float* __restrict__ w)  // (B,197) in d_out
{
    const int b = blockIdx.x;
    const int tid = threadIdx.x;  // 256 threads x 4 floats = 1024 H
    __shared__ float ws[197];
    if (tid < 197) ws[tid] = w[b * 197 + tid];
    __syncthreads();

    const int h0 = tid * 4;
    const float* base = Sp + (size_t)b * 196 * 1024 + h0;
    float4 acc = make_float4(0.f, 0.f, 0.f, 0.f);
#pragma unroll 4
    for (int p = 0; p < 196; p++) {
        float4 x = *(const float4*)(base + (size_t)p * 1024);
        float wp = ws[p];
        acc.x += x.x * wp; acc.y += x.y * wp;
        acc.z += x.z * wp; acc.w += x.w * wp;
    }
    const int idx = b * 1024 + h0;
    float4 sa = *(const float4*)&g_sent_aff[idx];
    float4 ha = *(const float4*)&g_hid_aff[idx];
    float wl = ws[196];
    acc.x += sa.x * wl + ha.x; acc.y += sa.y * wl + ha.y;
    acc.z += sa.z * wl + ha.z; acc.w += sa.w * wl + ha.w;
    *(float4*)&g_ctx[idx] = acc;
}

// ---------------- launcher ----------------
extern "C" void kernel_launch(void* const* d_in, const int* in_sizes, int n_in,
                              void* d_out, int out_size)
{
    (void)in_sizes; (void)n_in; (void)out_size;
    const float* spatial   = (const float*)d_in[0];
    const float* decoder   = (const float*)d_in[1];
    const float* st        = (const float*)d_in[2];
    const float* W_sen_aff = (const float*)d_in[3];
    const float* b_sen_aff = (const float*)d_in[4];
    const float* W_sen_att = (const float*)d_in[5];
    const float* b_sen_att = (const float*)d_in[6];
    const float* W_h_aff   = (const float*)d_in[7];
    const float* b_h_aff   = (const float*)d_in[8];
    const float* W_h_att   = (const float*)d_in[9];
    const float* b_h_att   = (const float*)d_in[10];
    const float* W_v_att   = (const float*)d_in[11];
    const float* b_v_att   = (const float*)d_in[12];
    const float* W_alpha   = (const float*)d_in[13];
    // d_in[14] = b_alpha: constant shift of all logits -> softmax-invariant, dropped
    const float* W_ctx     = (const float*)d_in[15];
    const float* b_ctx     = (const float*)d_in[16];

    float* out      = (float*)d_out;
    float* out_l    = out;                          // (256,1024)
    float* out_w    = out + Bz * Hz;                // (256,197)
    float* out_beta = out + Bz * Hz + Bz * 197;     // (256,1)

    float *sa, *ha, *st_att, *h_att, *ctx;
    cudaGetSymbolAddress((void**)&sa,     g_sent_aff);
    cudaGetSymbolAddress((void**)&ha,     g_hid_aff);
    cudaGetSymbolAddress((void**)&st_att, g_sent_att);
    cudaGetSymbolAddress((void**)&h_att,  g_hid_att);
    cudaGetSymbolAddress((void**)&ctx,    g_ctx);

    // sentinel_affine = relu(st @ W_sen_aff + b)
    gemm64<1><<<dim3(Hz / 64, Bz / 64), 256>>>(st, W_sen_aff, b_sen_aff, sa, Bz, Hz, Hz);
    // hidden_affine = tanh(dec @ W_h_aff + b)
    gemm64<2><<<dim3(Hz / 64, Bz / 64), 256>>>(decoder, W_h_aff, b_h_aff, ha, Bz, Hz, Hz);
    // sentinel_attn, hidden_attn
    gemm64<0><<<dim3(Az / 64, Bz / 64), 256>>>(sa, W_sen_att, b_sen_att, st_att, Bz, Az, Hz);
    gemm64<0><<<dim3(Az / 64, Bz / 64), 256>>>(ha, W_h_att, b_h_att, h_att, Bz, Az, Hz);
    // fused visual_attn GEMM + tanh + dot(W_alpha) -> alpha partials
    big_attn_kernel<<<dim3(MBIG / 128, 4), 256>>>(spatial, W_v_att, b_v_att, W_alpha);
    // softmax over 197 (incl. sentinel logit), writes weights+beta to d_out
    softmax_kernel<<<Bz, 256>>>(W_alpha, out_w, out_beta);
    // context + hidden_affine
    context_kernel<<<Bz, 256>>>(spatial, out_w);
    // out_l = tanh((context + hidden_affine) @ W_ctx + b_ctx)
    gemm64<2><<<dim3(Hz / 64, Bz / 64), 256>>>(ctx, W_ctx, b_ctx, out_l, Bz, Hz, Hz);
}

// round 3
// speedup vs baseline: 4.3243x; 4.3243x over previous
#include <cuda_runtime.h>
#include <cuda_fp16.h>
#include <math.h>
#include <stdint.h>

#define Bz   256
#define Pz   196
#define Hz   1024
#define Az   512
#define MBIG (Bz * Pz)   // 50176 = 392 * 128

// ------------------------------------------------------------------
// device scratch (allocations forbidden)
// ------------------------------------------------------------------
__device__ float  g_sent_aff[Bz * Hz];
__device__ float  g_hid_aff [Bz * Hz];
__device__ float  g_sent_att[Bz * Az];
__device__ float  g_hid_att [Bz * Az];
__device__ float  g_alpha_part[4 * MBIG];       // per-N-chunk partial alpha
__device__ float  g_ctx     [Bz * Hz];
__device__ float  g_aff_part[2 * 4 * Bz * Hz];  // split-K partials
__device__ float  g_att_part[2 * 4 * Bz * Az];
__device__ float  g_fin_part[4 * Bz * Hz];
__device__ __half g_Ah[(size_t)MBIG * Hz];      // spatial fp16 (103 MB)
__device__ __half g_Bh[Hz * Az];                // W_v_att fp16 [K][N]

// ------------------------------------------------------------------
__device__ __forceinline__ uint32_t smem_u32(const void* p) {
    uint32_t a;
    asm("{ .reg .u64 t; cvta.to.shared.u64 t, %1; cvt.u32.u64 %0, t; }"
        : "=r"(a) : "l"(p));
    return a;
}
__device__ __forceinline__ void cpa16(uint32_t dst, const void* src) {
    asm volatile("cp.async.cg.shared.global [%0], [%1], 16;"
                 :: "r"(dst), "l"(src) : "memory");
}
#define CP_COMMIT() asm volatile("cp.async.commit_group;" ::: "memory")
#define CP_WAIT(n)  asm volatile("cp.async.wait_group %0;" :: "n"(n) : "memory")

__device__ __forceinline__ void ldsm_x4(uint32_t* r, uint32_t addr) {
    asm volatile("ldmatrix.sync.aligned.m8n8.x4.shared.b16 {%0,%1,%2,%3}, [%4];"
                 : "=r"(r[0]), "=r"(r[1]), "=r"(r[2]), "=r"(r[3]) : "r"(addr));
}
__device__ __forceinline__ void ldsm_x4_t(uint32_t* r, uint32_t addr) {
    asm volatile("ldmatrix.sync.aligned.m8n8.x4.trans.shared.b16 {%0,%1,%2,%3}, [%4];"
                 : "=r"(r[0]), "=r"(r[1]), "=r"(r[2]), "=r"(r[3]) : "r"(addr));
}
__device__ __forceinline__ void mma16816(float* c, const uint32_t* a, const uint32_t* b) {
    asm volatile(
        "mma.sync.aligned.m16n8k16.row.col.f32.f16.f16.f32 "
        "{%0,%1,%2,%3}, {%4,%5,%6,%7}, {%8,%9}, {%0,%1,%2,%3};"
        : "+f"(c[0]), "+f"(c[1]), "+f"(c[2]), "+f"(c[3])
        : "r"(a[0]), "r"(a[1]), "r"(a[2]), "r"(a[3]), "r"(b[0]), "r"(b[1]));
}
__device__ __forceinline__ uint32_t tanh_f16x2(uint32_t x) {
    uint32_t y;
    asm("tanh.approx.f16x2 %0, %1;" : "=r"(y) : "r"(x));
    return y;
}

// ------------------------------------------------------------------
// fp32 -> fp16 conversions
// ------------------------------------------------------------------
__global__ void convA_kernel(const float* __restrict__ Sp) {
    size_t base = ((size_t)blockIdx.x * 256 + threadIdx.x) * 8;
    float4 x0 = *(const float4*)&Sp[base];
    float4 x1 = *(const float4*)&Sp[base + 4];
    __half2 h[4];
    h[0] = __floats2half2_rn(x0.x, x0.y);
    h[1] = __floats2half2_rn(x0.z, x0.w);
    h[2] = __floats2half2_rn(x1.x, x1.y);
    h[3] = __floats2half2_rn(x1.z, x1.w);
    *(uint4*)&g_Ah[base] = *(uint4*)h;
}
__global__ void convB_kernel(const float* __restrict__ Wv) {
    size_t base = ((size_t)blockIdx.x * 256 + threadIdx.x) * 8;
    float4 x0 = *(const float4*)&Wv[base];
    float4 x1 = *(const float4*)&Wv[base + 4];
    __half2 h[4];
    h[0] = __floats2half2_rn(x0.x, x0.y);
    h[1] = __floats2half2_rn(x0.z, x0.w);
    h[2] = __floats2half2_rn(x1.x, x1.y);
    h[3] = __floats2half2_rn(x1.z, x1.w);
    *(uint4*)&g_Bh[base] = *(uint4*)h;
}

// ------------------------------------------------------------------
// big fused attention GEMM on HMMA (mma.sync), BM=128 BN=128 BK=32
// grid = (392, 4), block = 256 (8 warps, 2M x 4N), 2 CTAs/SM
// dyn smem: 2 stages x (A 128x40h + B 32x136h) = 37888 B
// ------------------------------------------------------------------
#define AS_STRIDE 80    // bytes per A row (40 halves)
#define BS_STRIDE 272   // bytes per B row (136 halves)
#define AS_BYTES  10240 // 128*80
#define BS_BYTES  8704  // 32*272
#define STG_BYTES (AS_BYTES + BS_BYTES)

__global__ void __launch_bounds__(256, 2)
big_attn_mma(const float* __restrict__ bv,   // (512)
             const float* __restrict__ Wa)   // (512)
{
    extern __shared__ char dyn[];
    __shared__ float red[128 * 4];

    const int tid  = threadIdx.x;
    const int wid  = tid >> 5;
    const int lane = tid & 31;
    const int wm   = wid & 1;        // 2 warp rows (64 each)
    const int wn   = wid >> 1;       // 4 warp cols (32 each)
    const int m0   = blockIdx.x * 128;
    const int n0g  = blockIdx.y * 128;

    const uint32_t dyn_s = smem_u32(dyn);

    float acc[4][4][4] = {};

    // ---- cp.async prefetch helper (stage s <- k-chunk kc) ----
    auto prefetch = [&](int kc, int s) {
        const uint32_t as = dyn_s + s * STG_BYTES;
        const uint32_t bs = as + AS_BYTES;
        const int k0 = kc * 32;
        // A: 128 rows x 32 halves -> 512 x 16B, 2 per thread
#pragma unroll
        for (int g = 0; g < 2; g++) {
            int idx = g * 256 + tid;          // 0..511
            int row = idx >> 2, c = idx & 3;  // 4 x 16B per row
            cpa16(as + row * AS_STRIDE + c * 16,
                  &g_Ah[(size_t)(m0 + row) * 1024 + k0 + c * 8]);
        }
        // B: 32 rows x 128 halves -> 512 x 16B, 2 per thread
#pragma unroll
        for (int g = 0; g < 2; g++) {
            int idx = g * 256 + tid;
            int row = idx >> 4, c = idx & 15;
            cpa16(bs + row * BS_STRIDE + c * 16,
                  &g_Bh[(size_t)(k0 + row) * 512 + n0g + c * 8]);
        }
        CP_COMMIT();
    };

    prefetch(0, 0);

    for (int kc = 0; kc < 32; kc++) {
        const int s = kc & 1;
        if (kc < 31) prefetch(kc + 1, s ^ 1);
        if (kc < 31) { CP_WAIT(1); } else { CP_WAIT(0); }
        __syncthreads();

        const uint32_t as = dyn_s + s * STG_BYTES;
        const uint32_t bs = as + AS_BYTES;

#pragma unroll
        for (int k16 = 0; k16 < 2; k16++) {
            uint32_t a_frag[4][4];
            uint32_t b_frag[4][2];
#pragma unroll
            for (int mt = 0; mt < 4; mt++) {
                int row = wm * 64 + mt * 16 + (lane & 15);
                int col = k16 * 16 + ((lane >> 4) << 3);
                ldsm_x4(a_frag[mt], as + row * AS_STRIDE + col * 2);
            }
#pragma unroll
            for (int p = 0; p < 2; p++) {
                int krow = k16 * 16 + ((lane >> 3) & 1) * 8 + (lane & 7);
                int col  = wn * 32 + p * 16 + ((lane >> 4) << 3);
                uint32_t r[4];
                ldsm_x4_t(r, bs + krow * BS_STRIDE + col * 2);
                b_frag[2 * p][0] = r[0]; b_frag[2 * p][1] = r[1];
                b_frag[2 * p + 1][0] = r[2]; b_frag[2 * p + 1][1] = r[3];
            }
#pragma unroll
            for (int mt = 0; mt < 4; mt++)
#pragma unroll
                for (int nt = 0; nt < 4; nt++)
                    mma16816(acc[mt][nt], a_frag[mt], b_frag[nt]);
        }
        __syncthreads();
    }

    // ---- epilogue: alpha_part[m] = sum_n tanh(D + bv + hid_att) * Wa ----
    const int lane4 = lane & 3, laned4 = lane >> 2;
    // per-thread fixed cols: wn*32 + nt*8 + lane4*2 (+1)
    float bvv[8], waa[8];
#pragma unroll
    for (int nt = 0; nt < 4; nt++) {
        int ng = n0g + wn * 32 + nt * 8 + lane4 * 2;
        bvv[2 * nt] = bv[ng];     bvv[2 * nt + 1] = bv[ng + 1];
        waa[2 * nt] = Wa[ng];     waa[2 * nt + 1] = Wa[ng + 1];
    }
#pragma unroll
    for (int mt = 0; mt < 4; mt++) {
        float srow[2] = {0.f, 0.f};
#pragma unroll
        for (int h = 0; h < 2; h++) {
            int rloc = wm * 64 + mt * 16 + laned4 + h * 8;
            int bb = (m0 + rloc) / Pz;
            const float* ha = &g_hid_att[(size_t)bb * Az + n0g];
#pragma unroll
            for (int nt = 0; nt < 4; nt++) {
                int cl = wn * 32 + nt * 8 + lane4 * 2;
                float z0 = acc[mt][nt][2 * h]     + bvv[2 * nt]     + ha[cl];
                float z1 = acc[mt][nt][2 * h + 1] + bvv[2 * nt + 1] + ha[cl + 1];
                __half2 zh = __floats2half2_rn(z0, z1);
                uint32_t th = tanh_f16x2(*(uint32_t*)&zh);
                float2 tf = __half22float2(*(__half2*)&th);
                srow[h] += tf.x * waa[2 * nt] + tf.y * waa[2 * nt + 1];
            }
        }
        // reduce over the 4 lanes sharing each row (lane bits 0..1)
#pragma unroll
        for (int h = 0; h < 2; h++) {
            float s = srow[h];
            s += __shfl_xor_sync(0xffffffffu, s, 1);
            s += __shfl_xor_sync(0xffffffffu, s, 2);
            if (lane4 == 0) {
                int rloc = wm * 64 + mt * 16 + laned4 + h * 8;
                red[rloc * 4 + wn] = s;
            }
        }
    }
    __syncthreads();
    if (tid < 128) {
        float s = red[tid * 4] + red[tid * 4 + 1] + red[tid * 4 + 2] + red[tid * 4 + 3];
        g_alpha_part[(size_t)blockIdx.y * MBIG + m0 + tid] = s;
    }
}

// ------------------------------------------------------------------
// batched split-K fp32 GEMM: two jobs x 4 K-splits, 64x64 tiles
// ------------------------------------------------------------------
__global__ void gemm_splitk(const float* __restrict__ A0, const float* __restrict__ A1,
                            const float* __restrict__ W0, const float* __restrict__ W1,
                            float* __restrict__ part, int N)
{
    __shared__ __align__(16) float As[16][68];
    __shared__ __align__(16) float Bs[16][68];
    const int job = blockIdx.z >> 2, ks = blockIdx.z & 3;
    const float* A = job ? A1 : A0;
    const float* W = job ? W1 : W0;
    const int tid = threadIdx.x;
    const int tx = tid & 15, ty = tid >> 4;
    const int m0 = blockIdx.y * 64, n0 = blockIdx.x * 64;
    const int kbase = ks * 256;

    const int arow = tid >> 2, acg = (tid & 3) * 4;
    const int brow = tid >> 4, bcol = (tid & 15) * 4;

    float acc[4][4] = {};

    for (int k0 = kbase; k0 < kbase + 256; k0 += 16) {
        float4 av = *(const float4*)&A[(size_t)(m0 + arow) * 1024 + k0 + acg];
        As[acg + 0][arow] = av.x; As[acg + 1][arow] = av.y;
        As[acg + 2][arow] = av.z; As[acg + 3][arow] = av.w;
        *(float4*)&Bs[brow][bcol] =
            *(const float4*)&W[(size_t)(k0 + brow) * N + n0 + bcol];
        __syncthreads();
#pragma unroll
        for (int k = 0; k < 16; k++) {
            float4 a4 = *(const float4*)&As[k][ty * 4];
            float4 b4 = *(const float4*)&Bs[k][tx * 4];
            float a[4] = {a4.x, a4.y, a4.z, a4.w};
            float b[4] = {b4.x, b4.y, b4.z, b4.w};
#pragma unroll
            for (int i = 0; i < 4; i++)
#pragma unroll
                for (int j = 0; j < 4; j++) acc[i][j] += a[i] * b[j];
        }
        __syncthreads();
    }

    float* out = part + ((size_t)(job * 4 + ks) * 256) * N;
#pragma unroll
    for (int i = 0; i < 4; i++) {
        int m = m0 + ty * 4 + i;
#pragma unroll
        for (int j = 0; j < 4; j++)
            out[(size_t)m * N + n0 + tx * 4 + j] = acc[i][j];
    }
}

// combine split-K partials + bias + activation (0=none,1=relu,2=tanh)
__global__ void combine2(const float* __restrict__ part,
                         const float* __restrict__ b0, const float* __restrict__ b1,
                         float* __restrict__ o0, float* __restrict__ o1,
                         int N, int act0, int act1)
{
    const int job = blockIdx.y;
    const size_t e = ((size_t)blockIdx.x * 256 + threadIdx.x) * 4;
    const size_t slab = (size_t)256 * N;
    const float* p = part + (size_t)job * 4 * slab;
    float4 s = *(const float4*)(p + e);
    float4 s1 = *(const float4*)(p + slab + e);
    float4 s2 = *(const float4*)(p + 2 * slab + e);
    float4 s3 = *(const float4*)(p + 3 * slab + e);
    s.x += s1.x + s2.x + s3.x; s.y += s1.y + s2.y + s3.y;
    s.z += s1.z + s2.z + s3.z; s.w += s1.w + s2.w + s3.w;
    const int n = (int)(e & (size_t)(N - 1));
    const float* bb = job ? b1 : b0;
    float4 bvec = *(const float4*)&bb[n];
    s.x += bvec.x; s.y += bvec.y; s.z += bvec.z; s.w += bvec.w;
    int act = job ? act1 : act0;
    if (act == 1) {
        s.x = fmaxf(s.x, 0.f); s.y = fmaxf(s.y, 0.f);
        s.z = fmaxf(s.z, 0.f); s.w = fmaxf(s.w, 0.f);
    } else if (act == 2) {
        s.x = tanhf(s.x); s.y = tanhf(s.y); s.z = tanhf(s.z); s.w = tanhf(s.w);
    }
    float* o = job ? o1 : o0;
    *(float4*)(o + e) = s;
}

// ------------------------------------------------------------------
// softmax over 197 logits per batch (sentinel computed here, fp32 exact)
// ------------------------------------------------------------------
__global__ void softmax_kernel(const float* __restrict__ Wa,
                               float* __restrict__ out_w,
                               float* __restrict__ out_beta)
{
    const int b = blockIdx.x;
    const int tid = threadIdx.x;
    __shared__ float sh[256];
    __shared__ float vals[197];

    float s = 0.f;
    for (int a = tid; a < 512; a += 256)
        s += tanhf(g_sent_att[b * 512 + a] + g_hid_att[b * 512 + a]) * Wa[a];
    sh[tid] = s; __syncthreads();
    for (int off = 128; off > 0; off >>= 1) {
        if (tid < off) sh[tid] += sh[tid + off];
        __syncthreads();
    }
    float alpha_sent = sh[0];
    __syncthreads();

    float v = -INFINITY;
    if (tid < 196) {
        int m = b * 196 + tid;
        v = g_alpha_part[m] + g_alpha_part[MBIG + m] +
            g_alpha_part[2 * MBIG + m] + g_alpha_part[3 * MBIG + m];
        vals[tid] = v;
    } else if (tid == 196) {
        v = alpha_sent; vals[196] = v;
    }
    sh[tid] = v; __syncthreads();
    for (int off = 128; off > 0; off >>= 1) {
        if (tid < off) sh[tid] = fmaxf(sh[tid], sh[tid + off]);
        __syncthreads();
    }
    float mx = sh[0]; __syncthreads();

    float e = (tid < 197) ? expf(vals[tid] - mx) : 0.f;
    sh[tid] = e; __syncthreads();
    for (int off = 128; off > 0; off >>= 1) {
        if (tid < off) sh[tid] += sh[tid + off];
        __syncthreads();
    }
    float inv = 1.f / sh[0];
    if (tid < 197) {
        float w = e * inv;
        out_w[b * 197 + tid] = w;
        if (tid == 196) out_beta[b] = w;
    }
}

// ------------------------------------------------------------------
// context = weighted sum over P (fp32 spatial) + sentinel + hidden_affine
// ------------------------------------------------------------------
__global__ void context_kernel(const float* __restrict__ Sp,
                               const float* __restrict__ w)
{
    const int b = blockIdx.x;
    const int tid = threadIdx.x;
    __shared__ float ws[197];
    if (tid < 197) ws[tid] = w[b * 197 + tid];
    __syncthreads();

    const int h0 = tid * 4;
    const float* base = Sp + (size_t)b * 196 * 1024 + h0;
    float4 acc = make_float4(0.f, 0.f, 0.f, 0.f);
#pragma unroll 4
    for (int p = 0; p < 196; p++) {
        float4 x = *(const float4*)(base + (size_t)p * 1024);
        float wp = ws[p];
        acc.x += x.x * wp; acc.y += x.y * wp;
        acc.z += x.z * wp; acc.w += x.w * wp;
    }
    const int idx = b * 1024 + h0;
    float4 sa = *(const float4*)&g_sent_aff[idx];
    float4 ha = *(const float4*)&g_hid_aff[idx];
    float wl = ws[196];
    acc.x += sa.x * wl + ha.x; acc.y += sa.y * wl + ha.y;
    acc.z += sa.z * wl + ha.z; acc.w += sa.w * wl + ha.w;
    *(float4*)&g_ctx[idx] = acc;
}

// ------------------------------------------------------------------
extern "C" void kernel_launch(void* const* d_in, const int* in_sizes, int n_in,
                              void* d_out, int out_size)
{
    (void)in_sizes; (void)n_in; (void)out_size;
    const float* spatial   = (const float*)d_in[0];
    const float* decoder   = (const float*)d_in[1];
    const float* st        = (const float*)d_in[2];
    const float* W_sen_aff = (const float*)d_in[3];
    const float* b_sen_aff = (const float*)d_in[4];
    const float* W_sen_att = (const float*)d_in[5];
    const float* b_sen_att = (const float*)d_in[6];
    const float* W_h_aff   = (const float*)d_in[7];
    const float* b_h_aff   = (const float*)d_in[8];
    const float* W_h_att   = (const float*)d_in[9];
    const float* b_h_att   = (const float*)d_in[10];
    const float* W_v_att   = (const float*)d_in[11];
    const float* b_v_att   = (const float*)d_in[12];
    const float* W_alpha   = (const float*)d_in[13];
    // d_in[14] = b_alpha: softmax-invariant constant, dropped
    const float* W_ctx     = (const float*)d_in[15];
    const float* b_ctx     = (const float*)d_in[16];

    float* out      = (float*)d_out;
    float* out_l    = out;
    float* out_w    = out + Bz * Hz;
    float* out_beta = out + Bz * Hz + Bz * 197;

    float *sa, *ha, *st_att, *h_att, *ctx, *affp, *attp, *finp;
    cudaGetSymbolAddress((void**)&sa,     g_sent_aff);
    cudaGetSymbolAddress((void**)&ha,     g_hid_aff);
    cudaGetSymbolAddress((void**)&st_att, g_sent_att);
    cudaGetSymbolAddress((void**)&h_att,  g_hid_att);
    cudaGetSymbolAddress((void**)&ctx,    g_ctx);
    cudaGetSymbolAddress((void**)&affp,   g_aff_part);
    cudaGetSymbolAddress((void**)&attp,   g_att_part);
    cudaGetSymbolAddress((void**)&finp,   g_fin_part);

    const int BIG_SMEM = 2 * STG_BYTES;   // 37888
    cudaFuncSetAttribute(big_attn_mma,
                         cudaFuncAttributeMaxDynamicSharedMemorySize, BIG_SMEM);

    // fp32 -> fp16 pre-conversion of the big GEMM operands
    convA_kernel<<<25088, 256>>>(spatial);   // 25088*256*8 = 51,380,224
    convB_kernel<<<256, 256>>>(W_v_att);     // 256*256*8 = 524,288

    // sent_aff / hid_aff : split-K GEMMs + combine (relu / tanh)
    gemm_splitk<<<dim3(16, 4, 8), 256>>>(st, decoder, W_sen_aff, W_h_aff, affp, Hz);
    combine2<<<dim3(256, 2), 256>>>(affp, b_sen_aff, b_h_aff, sa, ha, Hz, 1, 2);

    // sent_att / hid_att
    gemm_splitk<<<dim3(8, 4, 8), 256>>>(sa, ha, W_sen_att, W_h_att, attp, Az);
    combine2<<<dim3(128, 2), 256>>>(attp, b_sen_att, b_h_att, st_att, h_att, Az, 0, 0);

    // fused visual-attention GEMM (HMMA) -> alpha partials (4 N-chunks)
    big_attn_mma<<<dim3(MBIG / 128, 4), 256, BIG_SMEM>>>(b_v_att, W_alpha);

    // softmax (197 incl. sentinel) -> weights + beta
    softmax_kernel<<<Bz, 256>>>(W_alpha, out_w, out_beta);

    // context + hidden_affine
    context_kernel<<<Bz, 256>>>(spatial, out_w);

    // out_l = tanh(ctx @ W_ctx + b_ctx)
    gemm_splitk<<<dim3(16, 4, 4), 256>>>(ctx, ctx, W_ctx, W_ctx, finp, Hz);
    combine2<<<dim3(256, 1), 256>>>(finp, b_ctx, b_ctx, out_l, out_l, Hz, 2, 2);
}